// round 1
// baseline (speedup 1.0000x reference)
#include <cuda_runtime.h>
#include <math.h>
#include <stdint.h>

// Problem constants
#define BB   64
#define MMAX 1024
#define DD   1024
#define HH   8
#define HDIM 128

// ---------------- scratch (device globals; no allocations allowed) ----------
__device__ float g_v2buf[67108864];   // [B*M, D] = 256 MB, normalized v2
__device__ float g_cos[BB * HH * MMAX];
__device__ float g_q[BB * DD];
__device__ float g_v1[BB * DD];
__device__ float g_qn[BB * HH];
__device__ float g_u[BB * HH * 64];

// ---------------- helpers ---------------------------------------------------
__device__ __forceinline__ void cp16(float* dst, const float* src, bool pred) {
    uint32_t d = (uint32_t)__cvta_generic_to_shared(dst);
    int n = pred ? 16 : 0;
    asm volatile("cp.async.ca.shared.global [%0], [%1], 16, %2;\n"
                 :: "r"(d), "l"(src), "r"(n));
}

__device__ __forceinline__ uint32_t f2tf(float f) {
    uint32_t u;
    asm("cvt.rna.tf32.f32 %0, %1;" : "=r"(u) : "f"(f));
    return u;
}

__device__ __forceinline__ void mma_tf32(float* d, const uint32_t* a, const uint32_t* b) {
    asm volatile(
        "mma.sync.aligned.m16n8k8.row.col.f32.tf32.tf32.f32 "
        "{%0,%1,%2,%3}, {%4,%5,%6,%7}, {%8,%9}, {%0,%1,%2,%3};"
        : "+f"(d[0]), "+f"(d[1]), "+f"(d[2]), "+f"(d[3])
        : "r"(a[0]), "r"(a[1]), "r"(a[2]), "r"(a[3]), "r"(b[0]), "r"(b[1]));
}

// ---------------- fused projection GEMM -------------------------------------
// C[row, col] = X[row, :] @ W[:, col]; tile 128x128, BK=16, tf32 mma.sync.
// Epilogue: +bias, CELU, GroupNorm over the 128-wide head chunk, gamma/beta.
// mode 0: store q + qn     mode 1: store v1
// mode 2: compute cos[b,h,m] only (k never materialized)
// mode 3: store v2 to scratch
#define AS_ST 20
#define BS_ST 136
#define CS_ST 133
#define GEMM_SMEM_BYTES 70144

__global__ void __launch_bounds__(256, 2)
proj_gemm(const float* __restrict__ X, const float* __restrict__ W,
          const float* __restrict__ bias, const float* __restrict__ gamma,
          const float* __restrict__ betav,
          int nrows, int mode,
          float* __restrict__ outbuf, float* __restrict__ qn_out,
          const float* __restrict__ qbuf, const float* __restrict__ qnbuf,
          float* __restrict__ cosbuf)
{
    extern __shared__ float sm[];
    float* As0 = sm;
    float* As1 = sm + 2560;
    float* Bs0 = sm + 5120;
    float* Bs1 = sm + 7296;
    float* Cs     = sm;            // reused after mainloop
    float* bias_s = sm + 17024;
    float* gam_s  = sm + 17152;
    float* bet_s  = sm + 17280;
    float* q_s    = sm + 17408;

    const int tid  = threadIdx.x;
    const int lane = tid & 31, wid = tid >> 5;
    const int wr = wid >> 2, wc = wid & 3;     // warp grid 2x4 (64x32 per warp)
    const int g = lane >> 2, t = lane & 3;
    const int rowbase = blockIdx.x * 128;
    const int colbase = blockIdx.y * 128;

    if (tid < 128) {
        bias_s[tid] = bias[colbase + tid];
        gam_s[tid]  = gamma[colbase + tid];
        bet_s[tid]  = betav[colbase + tid];
        if (mode == 2) q_s[tid] = qbuf[(size_t)(rowbase >> 10) * DD + colbase + tid];
    }

    float acc[4][4][4];
#pragma unroll
    for (int i = 0; i < 4; i++)
#pragma unroll
        for (int j = 0; j < 4; j++)
#pragma unroll
            for (int k = 0; k < 4; k++) acc[i][j][k] = 0.f;

    const int ar  = tid >> 2;          // A row (0..63), +64 second pass
    const int akq = (tid & 3) * 4;     // A k-offset (float4)
    const int bk  = tid >> 5;          // B k row (0..7), +8 second pass
    const int bnq = (tid & 31) * 4;    // B n-offset (float4)

    auto load_tiles = [&](int k0, float* as, float* bs) {
#pragma unroll
        for (int i = 0; i < 2; i++) {
            int r = ar + i * 64;
            bool p = (rowbase + r) < nrows;
            const float* src = X + (size_t)(rowbase + r) * DD + k0 + akq;
            cp16(as + r * AS_ST + akq, p ? src : X, p);
        }
#pragma unroll
        for (int i = 0; i < 2; i++) {
            int k = bk + i * 8;
            const float* src = W + (size_t)(k0 + k) * DD + colbase + bnq;
            cp16(bs + k * BS_ST + bnq, src, true);
        }
    };

    load_tiles(0, As0, Bs0);
    asm volatile("cp.async.commit_group;");

    int cur = 0;
    for (int kt = 0; kt < 64; kt++) {
        if (kt < 63) {
            load_tiles((kt + 1) * 16, cur ? As0 : As1, cur ? Bs0 : Bs1);
            asm volatile("cp.async.commit_group;");
            asm volatile("cp.async.wait_group 1;");
        } else {
            asm volatile("cp.async.wait_group 0;");
        }
        __syncthreads();

        const float* as = cur ? As1 : As0;
        const float* bs = cur ? Bs1 : Bs0;
#pragma unroll
        for (int ks = 0; ks < 2; ks++) {
            uint32_t af[4][4], bf[4][2];
#pragma unroll
            for (int mt = 0; mt < 4; mt++) {
                int r = wr * 64 + mt * 16 + g;
                int c = ks * 8 + t;
                af[mt][0] = f2tf(as[r * AS_ST + c]);
                af[mt][1] = f2tf(as[(r + 8) * AS_ST + c]);
                af[mt][2] = f2tf(as[r * AS_ST + c + 4]);
                af[mt][3] = f2tf(as[(r + 8) * AS_ST + c + 4]);
            }
#pragma unroll
            for (int nt = 0; nt < 4; nt++) {
                int n = wc * 32 + nt * 8 + g;
                int k = ks * 8 + t;
                bf[nt][0] = f2tf(bs[k * BS_ST + n]);
                bf[nt][1] = f2tf(bs[(k + 4) * BS_ST + n]);
            }
#pragma unroll
            for (int mt = 0; mt < 4; mt++)
#pragma unroll
                for (int nt = 0; nt < 4; nt++)
                    mma_tf32(acc[mt][nt], af[mt], bf[nt]);
        }
        __syncthreads();
        cur ^= 1;
    }

    // ---- write accumulators to smem tile ----
#pragma unroll
    for (int mt = 0; mt < 4; mt++) {
        int r = wr * 64 + mt * 16 + g;
#pragma unroll
        for (int nt = 0; nt < 4; nt++) {
            int cc = wc * 32 + nt * 8 + t * 2;
            Cs[r * CS_ST + cc]           = acc[mt][nt][0];
            Cs[r * CS_ST + cc + 1]       = acc[mt][nt][1];
            Cs[(r + 8) * CS_ST + cc]     = acc[mt][nt][2];
            Cs[(r + 8) * CS_ST + cc + 1] = acc[mt][nt][3];
        }
    }
    __syncthreads();

    // ---- per-row epilogue: bias + CELU + GroupNorm (+ mode-specific) ----
    if (tid < 128) {
        int r = tid;
        int row_g = rowbase + r;
        if (row_g < nrows) {
            float* row = Cs + r * CS_ST;
            float s = 0.f, s2 = 0.f;
#pragma unroll 4
            for (int c = 0; c < 128; c++) {
                float y = row[c] + bias_s[c];
                if (y < 0.f) y = 1.3f * expm1f(y * (1.0f / 1.3f));
                row[c] = y;
                s += y; s2 += y * y;
            }
            float mu  = s * (1.f / 128.f);
            float var = fmaxf(s2 * (1.f / 128.f) - mu * mu, 0.f);
            float rs  = rsqrtf(var + 1e-5f);

            if (mode == 2) {
                float kn2 = 0.f, dot = 0.f;
#pragma unroll 4
                for (int c = 0; c < 128; c++) {
                    float v = (row[c] - mu) * rs * gam_s[c] + bet_s[c];
                    kn2 += v * v;
                    dot += v * q_s[c];
                }
                int b = row_g >> 10;
                float qn = qnbuf[b * HH + blockIdx.y];
                float cosv = dot / (fmaxf(qn, 1e-8f) * fmaxf(sqrtf(kn2), 1e-8f));
                cosbuf[(size_t)(b * HH + blockIdx.y) * MMAX + (row_g & (MMAX - 1))] = cosv;
            } else {
                float n2 = 0.f;
#pragma unroll 4
                for (int c = 0; c < 128; c++) {
                    float v = (row[c] - mu) * rs * gam_s[c] + bet_s[c];
                    row[c] = v;
                    n2 += v * v;
                }
                if (mode == 0) qn_out[row_g * HH + blockIdx.y] = sqrtf(n2);
            }
        }
    }
    __syncthreads();

    if (mode != 2) {
        for (int idx = tid; idx < 128 * 128; idx += 256) {
            int r = idx >> 7, c = idx & 127;
            int row_g = rowbase + r;
            if (row_g < nrows)
                outbuf[(size_t)row_g * DD + colbase + c] = Cs[r * CS_ST + c];
        }
    }
}

// ---------------- u = (q / max(qn,1e-12)) @ W1  (tiny) ----------------------
__global__ void u_kernel(const float* __restrict__ qbuf, const float* __restrict__ qn,
                         const float* __restrict__ W1, float* __restrict__ u)
{
    int bh = blockIdx.x;          // 512
    int j  = threadIdx.x;         // 64
    int b = bh >> 3, h = bh & 7;
    const float* q = qbuf + (size_t)b * DD + h * HDIM;
    float a = 0.f;
#pragma unroll 8
    for (int d = 0; d < 128; d++) a += q[d] * W1[d * 64 + j];
    u[bh * 64 + j] = a / fmaxf(qn[bh], 1e-12f);
}

// ---------------- finalize: am/pool/softmax/a_ch/v2o/output ------------------
__device__ __forceinline__ float blk_red(float v, bool ismax, float* red, int tid) {
    int lane = tid & 31, wid = tid >> 5;
#pragma unroll
    for (int o = 16; o; o >>= 1) {
        float tv = __shfl_xor_sync(0xffffffffu, v, o);
        v = ismax ? fmaxf(v, tv) : (v + tv);
    }
    __syncthreads();
    if (lane == 0) red[wid] = v;
    __syncthreads();
    float r = red[0];
#pragma unroll
    for (int w = 1; w < 8; w++) r = ismax ? fmaxf(r, red[w]) : (r + red[w]);
    return r;
}

__global__ void __launch_bounds__(256)
finalize_kernel(const float* __restrict__ cosbuf, const float* __restrict__ mask,
                const float* __restrict__ u, const float* __restrict__ b1,
                const float* __restrict__ Wl, const float* __restrict__ bl,
                const float* __restrict__ Wl2, const float* __restrict__ bl2,
                const float* __restrict__ v1buf, const float* __restrict__ v2buf,
                float* __restrict__ out)
{
    __shared__ float u_s[64], b1_s[64], wl_s[64];
    __shared__ float logits[1024];
    __shared__ float poolpart[8][64];
    __shared__ float pool_s[64];
    __shared__ float red[8];
    __shared__ float ach_s[128];
    __shared__ float v2o_s[256];

    const int tid = threadIdx.x, lane = tid & 31, wid = tid >> 5;
    const int bh = blockIdx.x, b = bh >> 3, h = bh & 7;

    if (tid < 64) {
        u_s[tid]  = u[bh * 64 + tid];
        b1_s[tid] = b1[tid];
        wl_s[tid] = Wl[tid];
    }
    __syncthreads();

    // sum of mask over m (per b)
    float msum = 0.f;
    for (int m = tid; m < 1024; m += 256) msum += mask[b * 1024 + m];
    msum = blk_red(msum, false, red, tid);

    // am = relu(cos_m * u_j + b1_j); pool partials + sparse-attn logits
    const float blv = bl[0];
    float u0 = u_s[lane],  u1 = u_s[lane + 32];
    float c0 = b1_s[lane], c1 = b1_s[lane + 32];
    float w0 = wl_s[lane], w1 = wl_s[lane + 32];
    float pj0 = 0.f, pj1 = 0.f;
    for (int m = wid * 128; m < wid * 128 + 128; m++) {
        float cv = cosbuf[(size_t)bh * 1024 + m];
        float mk = mask[b * 1024 + m];
        float a0 = fmaxf(cv * u0 + c0, 0.f);
        float a1 = fmaxf(cv * u1 + c1, 0.f);
        pj0 += mk * a0; pj1 += mk * a1;
        float sp = a0 * w0 + a1 * w1;
#pragma unroll
        for (int o = 16; o; o >>= 1) sp += __shfl_xor_sync(0xffffffffu, sp, o);
        if (lane == 0) logits[m] = (mk == 0.f) ? -1e9f : (sp + blv);
    }
    poolpart[wid][lane]      = pj0;
    poolpart[wid][lane + 32] = pj1;
    __syncthreads();
    if (tid < 64) {
        float s = 0.f;
#pragma unroll
        for (int w = 0; w < 8; w++) s += poolpart[w][tid];
        pool_s[tid] = s / msum;
    }

    // softmax over m
    float lm = -1e30f;
    for (int m = tid; m < 1024; m += 256) lm = fmaxf(lm, logits[m]);
    lm = blk_red(lm, true, red, tid);
    float es = 0.f;
    for (int m = tid; m < 1024; m += 256) {
        float e = expf(logits[m] - lm);
        logits[m] = e;
        es += e;
    }
    es = blk_red(es, false, red, tid);
    float inv = 1.f / es;

    // channel gate
    if (tid < 128) {
        float a = bl2[tid];
#pragma unroll 8
        for (int j = 0; j < 64; j++) a += pool_s[j] * Wl2[j * 128 + tid];
        ach_s[tid] = 1.f / (1.f + expf(-a));
    }

    // v2o = softmax(m) . v2   (heavy read, coalesced across d)
    int d = tid & 127, grp = tid >> 7;
    const float* v2p = v2buf + (size_t)b * 1024 * 1024 + (size_t)h * 128 + d;
    float acc = 0.f;
    for (int m = grp * 512; m < grp * 512 + 512; m++)
        acc += logits[m] * v2p[(size_t)m * 1024];
    v2o_s[tid] = acc;
    __syncthreads();

    if (tid < 128) {
        float vo = (v2o_s[tid] + v2o_s[tid + 128]) * inv;
        int idx = b * 1024 + h * 128 + tid;
        out[idx] = v1buf[idx] * vo * ach_s[tid];
    }
}

// ---------------- launcher ---------------------------------------------------
extern "C" void kernel_launch(void* const* d_in, const int* in_sizes, int n_in,
                              void* d_out, int out_size)
{
    const float* query   = (const float*)d_in[0];
    const float* key     = (const float*)d_in[1];
    const float* mask    = (const float*)d_in[2];
    const float* value1  = (const float*)d_in[3];
    const float* value2  = (const float*)d_in[4];
    const float* W_q     = (const float*)d_in[5];
    const float* b_q     = (const float*)d_in[6];
    const float* g_qg    = (const float*)d_in[7];
    const float* be_q    = (const float*)d_in[8];
    const float* W_k     = (const float*)d_in[9];
    const float* b_k     = (const float*)d_in[10];
    const float* g_kg    = (const float*)d_in[11];
    const float* be_k    = (const float*)d_in[12];
    const float* W_v1    = (const float*)d_in[13];
    const float* b_v1    = (const float*)d_in[14];
    const float* g_v1g   = (const float*)d_in[15];
    const float* be_v1   = (const float*)d_in[16];
    const float* W_v2    = (const float*)d_in[17];
    const float* b_v2    = (const float*)d_in[18];
    const float* g_v2g   = (const float*)d_in[19];
    const float* be_v2   = (const float*)d_in[20];
    const float* W1      = (const float*)d_in[21];
    const float* b1      = (const float*)d_in[22];
    const float* Wl      = (const float*)d_in[23];
    const float* bl      = (const float*)d_in[24];
    const float* Wl2     = (const float*)d_in[25];
    const float* bl2     = (const float*)d_in[26];
    float* out = (float*)d_out;

    float *v2buf, *cosb, *qb, *v1b, *qnb, *ub;
    cudaGetSymbolAddress((void**)&v2buf, g_v2buf);
    cudaGetSymbolAddress((void**)&cosb,  g_cos);
    cudaGetSymbolAddress((void**)&qb,    g_q);
    cudaGetSymbolAddress((void**)&v1b,   g_v1);
    cudaGetSymbolAddress((void**)&qnb,   g_qn);
    cudaGetSymbolAddress((void**)&ub,    g_u);

    cudaFuncSetAttribute(proj_gemm, cudaFuncAttributeMaxDynamicSharedMemorySize,
                         GEMM_SMEM_BYTES);

    dim3 blk(256);
    dim3 gsmall(1, 8);
    dim3 gbig(512, 8);

    // q projection (+ qn)
    proj_gemm<<<gsmall, blk, GEMM_SMEM_BYTES>>>(
        query, W_q, b_q, g_qg, be_q, 64, 0, qb, qnb, nullptr, nullptr, nullptr);
    // v1 projection
    proj_gemm<<<gsmall, blk, GEMM_SMEM_BYTES>>>(
        value1, W_v1, b_v1, g_v1g, be_v1, 64, 1, v1b, nullptr, nullptr, nullptr, nullptr);
    // u = q_dir @ W1
    u_kernel<<<512, 64>>>(qb, qnb, W1, ub);
    // k projection fused to cos (k never materialized)
    proj_gemm<<<gbig, blk, GEMM_SMEM_BYTES>>>(
        key, W_k, b_k, g_kg, be_k, 65536, 2, nullptr, nullptr, qb, qnb, cosb);
    // v2 projection -> scratch
    proj_gemm<<<gbig, blk, GEMM_SMEM_BYTES>>>(
        value2, W_v2, b_v2, g_v2g, be_v2, 65536, 3, v2buf, nullptr, nullptr, nullptr, nullptr);
    // pool / softmax / gates / weighted sum / output
    finalize_kernel<<<512, blk>>>(cosb, mask, ub, b1, Wl, bl, Wl2, bl2, v1b, v2buf, out);
}